// round 15
// baseline (speedup 1.0000x reference)
#include <cuda_runtime.h>
#include <cuda_fp16.h>
#include <cstdint>

#define NWARPS 12
#define THREADS 384
#define FULLMASK 0xffffffffu

// ---- smem byte map ----
// [0, 62976)    per-tile region: A-tile fp16 [96 x 328h] (stride 656 B) during
//               stage B; after MMA reused as:
//                 [0, 26112)      s1 fp16 [96 x 136h] (stride 272 B)
//                 [26624, 40448)  gate pre-sigmoid fp32 [96 x 36]
//                 [40448, 41216)  partB_sm [96 x 2] fp32
// [62976, 146944)  BT  = Ws1^T fp16 [128 x 328h] (stride 656 B), persistent
// [146944, 155648) WG1T = Wg1^T fp16 [32 x 136h] (stride 272 B), persistent
// [155648, 205568) fp32 weights (12480 floats)
// [205568, 224000) scratch: 12 warps x 384 floats
#define AB_OFF    0
#define A_STRIDE_B 656
#define S1H_STRIDE 272
#define GOUT_OFF  26624
#define GOUT_STRIDE 36
#define PB_OFF    40448
#define BT_OFF    62976
#define WG1T_OFF  146944
#define FW_OFF    155648
#define F_WV11    0
#define F_WV21    4096
#define F_WG1     6144
#define F_BG1     10240
#define F_WD1     10272
#define F_WV12    11296
#define F_WS2     12320
#define SCR_OFF   205568
#define WS_FLOATS 384
#define SMEM_BYTES 224000

typedef unsigned long long u64;
typedef unsigned int u32;

__device__ __forceinline__ u64 pk2(float x, float y){u64 d;asm("mov.b64 %0,{%1,%2};":"=l"(d):"f"(x),"f"(y));return d;}
__device__ __forceinline__ void upk2(float&x,float&y,u64 d){asm("mov.b64 {%0,%1},%2;":"=f"(x),"=f"(y):"l"(d));}
__device__ __forceinline__ void fma2(u64&a,u64 x,u64 w){asm("fma.rn.f32x2 %0,%1,%2,%3;":"=l"(a):"l"(x),"l"(w),"l"(a));}
__device__ __forceinline__ float fcomp(const float4&v,int e){return (&v.x)[e];}
__device__ __forceinline__ float lrelu(float x){return (x>=0.f)?x:0.01f*x;}

__device__ __forceinline__ u32 smem_u32(const void* p){
    u32 a; asm("{ .reg .u64 t; cvta.to.shared.u64 t, %1; cvt.u32.u64 %0, t; }":"=r"(a):"l"(p)); return a;
}
__device__ __forceinline__ void ldm_x4(u32& r0,u32& r1,u32& r2,u32& r3,u32 addr){
    asm volatile("ldmatrix.sync.aligned.m8n8.x4.shared.b16 {%0,%1,%2,%3}, [%4];"
        : "=r"(r0),"=r"(r1),"=r"(r2),"=r"(r3) : "r"(addr));
}
__device__ __forceinline__ void mma16816(float* c,u32 a0,u32 a1,u32 a2,u32 a3,u32 b0,u32 b1){
    asm volatile("mma.sync.aligned.m16n8k16.row.col.f32.f16.f16.f32 "
        "{%0,%1,%2,%3},{%4,%5,%6,%7},{%8,%9},{%0,%1,%2,%3};"
        : "+f"(c[0]),"+f"(c[1]),"+f"(c[2]),"+f"(c[3])
        : "r"(a0),"r"(a1),"r"(a2),"r"(a3),"r"(b0),"r"(b1));
}

__global__ __launch_bounds__(THREADS, 1)
void frontier_vn_kernel(
    const float* __restrict__ g_sca, const float* __restrict__ g_vec,
    const int* __restrict__ g_idx,
    const float* __restrict__ gWv11, const float* __restrict__ gWv21,
    const float* __restrict__ gWs1,  const float* __restrict__ gWg1,
    const float* __restrict__ gbg1,  const float* __restrict__ gWd1,
    const float* __restrict__ gWv12, const float* __restrict__ gWs2,
    float* __restrict__ out, int M)
{
    extern __shared__ char smc[];
    float* fw    = (float*)(smc + FW_OFF);
    float* sWv11 = fw + F_WV11;
    float* sWv21 = fw + F_WV21;
    float* sbg1  = fw + F_BG1;
    float* sWd1  = fw + F_WD1;
    float* sWv12 = fw + F_WV12;
    float* sWs2  = fw + F_WS2;
    float* gate_sm = (float*)(smc + GOUT_OFF);
    float* partB_sm = (float*)(smc + PB_OFF);

    const int tid = threadIdx.x, warp = tid>>5, lane = tid&31;
    const u32 sbu = smem_u32(smc);

    // ---- one-time init ----
    for (int i = tid; i < 40960; i += THREADS) {         // BT = Ws1^T fp16
        int k = i >> 7, j = i & 127;
        *(__half*)(smc + BT_OFF + j*A_STRIDE_B + k*2) = __float2half(gWs1[i]);
    }
    for (int i = tid; i < 4096; i += THREADS) {          // WG1T = Wg1^T fp16
        int k = i >> 5, o = i & 31;
        *(__half*)(smc + WG1T_OFF + o*S1H_STRIDE + k*2) = __float2half(gWg1[i]);
    }
    {
        float4* d; const float4* s;
        d=(float4*)sWv11; s=(const float4*)gWv11; for(int i=tid;i<1024;i+=THREADS) d[i]=s[i];
        d=(float4*)sWv21; s=(const float4*)gWv21; for(int i=tid;i<512; i+=THREADS) d[i]=s[i];
        d=(float4*)sbg1;  s=(const float4*)gbg1;  for(int i=tid;i<8;   i+=THREADS) d[i]=s[i];
        d=(float4*)sWd1;  s=(const float4*)gWd1;  for(int i=tid;i<256; i+=THREADS) d[i]=s[i];
        d=(float4*)sWv12; s=(const float4*)gWv12; for(int i=tid;i<256; i+=THREADS) d[i]=s[i];
        d=(float4*)sWs2;  s=(const float4*)gWs2;  for(int i=tid;i<40;  i+=THREADS) d[i]=s[i];
    }
    __syncthreads();

    float* ws = (float*)(smc + SCR_OFF) + warp * WS_FLOATS;
    float4* wsv4 = (float4*)ws;
    const float2* sWv11_f2 = (const float2*)sWv11;
    const float4* g_sca4 = (const float4*)g_sca;
    const float4* g_vec4 = (const float4*)g_vec;

    const int r_ln = lane >> 2, q_ln = lane & 3;
    const int pblk = warp >> 1;      // 16-row block (stage B + gate)
    const int jhalf = warp & 1;      // stage B: 64-col half; gate: 16-col half
    const float w2head = sWs2[lane];

    // ldmatrix bases (patterns verified in v14)
    const u32 a_base = sbu + AB_OFF
        + (u32)(pblk*16 + (lane&7) + ((lane>>3)&1)*8) * A_STRIDE_B
        + (u32)(lane>>4) * 16;
    const u32 b_base = sbu + BT_OFF
        + (u32)(jhalf*64 + (lane&7) + (lane>>4)*8) * A_STRIDE_B
        + (u32)((lane>>3)&1) * 16;
    const u32 ag_base = sbu + AB_OFF
        + (u32)(pblk*16 + (lane&7) + ((lane>>3)&1)*8) * S1H_STRIDE
        + (u32)(lane>>4) * 16;
    const u32 bg_base = sbu + WG1T_OFF
        + (u32)(jhalf*16 + (lane&7) + (lane>>4)*8) * S1H_STRIDE
        + (u32)((lane>>3)&1) * 16;

    for (int tile = blockIdx.x * 96; tile < M; tile += gridDim.x * 96)
    {
        const int base = tile + warp * 8;
        int m_dyn = base + r_ln;
        const int idx_dyn = g_idx[(m_dyn < M) ? m_dyn : (M - 1)];
        const size_t vbase = (size_t)idx_dyn * 48;
        const size_t sbase = (size_t)idx_dyn * 64;

        // ===== Stage A (v5): vec -> vh in registers =====
        u64 pax[8], pay[8], paz[8];
        #pragma unroll
        for (int r = 0; r < 8; r++) { pax[r]=0ull; pay[r]=0ull; paz[r]=0ull; }
        float4 vf0 = g_vec4[vbase + 3*q_ln + 0];
        float4 vf1 = g_vec4[vbase + 3*q_ln + 1];
        float4 vf2 = g_vec4[vbase + 3*q_ln + 2];
        for (int chunk = 0; chunk < 4; chunk++) {
            __syncwarp();
            wsv4[r_ln*12 + 3*q_ln + 0] = vf0;
            wsv4[r_ln*12 + 3*q_ln + 1] = vf1;
            wsv4[r_ln*12 + 3*q_ln + 2] = vf2;
            if (chunk < 3) {
                vf0 = g_vec4[vbase + (chunk+1)*12 + 3*q_ln + 0];
                vf1 = g_vec4[vbase + (chunk+1)*12 + 3*q_ln + 1];
                vf2 = g_vec4[vbase + (chunk+1)*12 + 3*q_ln + 2];
            }
            __syncwarp();
            for (int cq = 0; cq < 4; cq++) {
                u64 ww[4];
                #pragma unroll
                for (int e = 0; e < 4; e++) {
                    float2 w2 = sWv11_f2[(chunk*16 + cq*4 + e)*32 + lane];
                    ww[e] = pk2(w2.x, w2.y);
                }
                #pragma unroll
                for (int r = 0; r < 8; r++) {
                    float4 f0 = wsv4[r*12 + 3*cq + 0];
                    float4 f1 = wsv4[r*12 + 3*cq + 1];
                    float4 f2 = wsv4[r*12 + 3*cq + 2];
                    float vcx[4] = {f0.x, f0.w, f1.z, f2.y};
                    float vcy[4] = {f0.y, f1.x, f1.w, f2.z};
                    float vcz[4] = {f0.z, f1.y, f2.x, f2.w};
                    #pragma unroll
                    for (int e = 0; e < 4; e++) {
                        fma2(pax[r], pk2(vcx[e], vcx[e]), ww[e]);
                        fma2(pay[r], pk2(vcy[e], vcy[e]), ww[e]);
                        fma2(paz[r], pk2(vcz[e], vcz[e]), ww[e]);
                    }
                }
            }
        }

        // ===== A-tile staging (fp16, row-major, stride 656 B) =====
        #pragma unroll
        for (int r = 0; r < 8; r++) {
            float x0,x1,y0,y1,z0,z1;
            upk2(x0,x1,pax[r]); upk2(y0,y1,pay[r]); upk2(z0,z1,paz[r]);
            __half2 nn = __floats2half2_rn(sqrtf(x0*x0+y0*y0+z0*z0),
                                           sqrtf(x1*x1+y1*y1+z1*z1));
            *(__half2*)(smc + (warp*8 + r)*A_STRIDE_B + lane*4) = nn;
        }
        {
            const int mrow = warp*8 + r_ln;
            #pragma unroll
            for (int pass = 0; pass < 8; pass++) {
                float4 a = g_sca4[sbase + pass*8 + q_ln*2];
                float4 b = g_sca4[sbase + pass*8 + q_ln*2 + 1];
                __half2 h0 = __floats2half2_rn(a.x, a.y);
                __half2 h1 = __floats2half2_rn(a.z, a.w);
                __half2 h2 = __floats2half2_rn(b.x, b.y);
                __half2 h3 = __floats2half2_rn(b.z, b.w);
                uint4 v;
                v.x = *(u32*)&h0; v.y = *(u32*)&h1;
                v.z = *(u32*)&h2; v.w = *(u32*)&h3;
                *(uint4*)(smc + mrow*A_STRIDE_B + 128 + pass*64 + q_ln*16) = v;
            }
        }
        __syncthreads();

        // ===== Stage B: HMMA [pblk*16,+16) x [jhalf*64,+64) =====
        float cacc[32];
        #pragma unroll
        for (int i = 0; i < 32; i++) cacc[i] = 0.f;
        #pragma unroll
        for (int ks = 0; ks < 20; ks++) {
            u32 a0,a1,a2,a3;
            ldm_x4(a0,a1,a2,a3, a_base + ks*32);
            #pragma unroll
            for (int jb2 = 0; jb2 < 4; jb2++) {
                u32 b0,b1,b2,b3;
                ldm_x4(b0,b1,b2,b3, b_base + jb2*(16*A_STRIDE_B) + ks*32);
                mma16816(cacc + (jb2*2+0)*4, a0,a1,a2,a3, b0,b1);
                mma16816(cacc + (jb2*2+1)*4, a0,a1,a2,a3, b2,b3);
            }
        }
        __syncthreads();   // A-tile dead; region becomes s1f16/gate/partB

        // ===== s1 -> fp16 tile + partB from cacc =====
        {
            int row0 = pblk*16 + (lane>>2);
            int colb = jhalf*64 + 2*(lane&3);
            float pa = 0.f, pb = 0.f;
            #pragma unroll
            for (int jb = 0; jb < 8; jb++) {
                int col = colb + jb*8;
                __half2 h0 = __floats2half2_rn(cacc[jb*4+0], cacc[jb*4+1]);
                __half2 h1 = __floats2half2_rn(cacc[jb*4+2], cacc[jb*4+3]);
                *(__half2*)(smc + row0*S1H_STRIDE + col*2)      = h0;
                *(__half2*)(smc + (row0+8)*S1H_STRIDE + col*2)  = h1;
                float2 wt = *(const float2*)(sWs2 + 32 + col);
                pa += lrelu(cacc[jb*4+0])*wt.x + lrelu(cacc[jb*4+1])*wt.y;
                pb += lrelu(cacc[jb*4+2])*wt.x + lrelu(cacc[jb*4+3])*wt.y;
            }
            pa += __shfl_xor_sync(FULLMASK, pa, 1);
            pa += __shfl_xor_sync(FULLMASK, pa, 2);
            pb += __shfl_xor_sync(FULLMASK, pb, 1);
            pb += __shfl_xor_sync(FULLMASK, pb, 2);
            if ((lane & 3) == 0) {
                partB_sm[row0*2 + jhalf]     = pa;
                partB_sm[(row0+8)*2 + jhalf] = pb;
            }
        }
        __syncthreads();

        // ===== Gate HMMA: [96x128]@[128x32]; warp = rows [pblk*16,+16), cols [jhalf*16,+16) =====
        {
            float gacc[8];
            #pragma unroll
            for (int i = 0; i < 8; i++) gacc[i] = 0.f;
            #pragma unroll
            for (int ks = 0; ks < 8; ks++) {
                u32 a0,a1,a2,a3, b0,b1,b2,b3;
                ldm_x4(a0,a1,a2,a3, ag_base + ks*32);
                ldm_x4(b0,b1,b2,b3, bg_base + ks*32);
                mma16816(gacc + 0, a0,a1,a2,a3, b0,b1);
                mma16816(gacc + 4, a0,a1,a2,a3, b2,b3);
            }
            int row0 = pblk*16 + (lane>>2);
            int col0 = jhalf*16 + 2*(lane&3);
            #pragma unroll
            for (int nb = 0; nb < 2; nb++) {
                *(float2*)(gate_sm + row0*GOUT_STRIDE + col0 + nb*8)
                    = make_float2(gacc[nb*4+0], gacc[nb*4+1]);
                *(float2*)(gate_sm + (row0+8)*GOUT_STRIDE + col0 + nb*8)
                    = make_float2(gacc[nb*4+2], gacc[nb*4+3]);
            }
        }
        __syncthreads();

        // sigmoid: warp reads its 8 rows, col = lane
        float ggf[8];
        {
            float bias = sbg1[lane];
            #pragma unroll
            for (int r = 0; r < 8; r++) {
                float g = gate_sm[(warp*8 + r)*GOUT_STRIDE + lane];
                ggf[r] = 1.f/(1.f+__expf(-(g + bias)));
            }
        }

        // ===== Stages D/E/F (v5) =====
        #pragma unroll
        for (int p = 0; p < 2; p++) {
            u64 oxy[4] = {0ull,0ull,0ull,0ull};
            float ozv[4] = {0.f,0.f,0.f,0.f};
            #pragma unroll
            for (int t = 0; t < 2; t++) {
                __syncwarp();
                if ((lane >> 4) == t) {
                    int h0 = 2*lane - 32*t;
                    #pragma unroll
                    for (int r2 = 0; r2 < 4; r2++) {
                        *(u64*)(ws + r2*96 +  0 + h0) = pax[p*4+r2];
                        *(u64*)(ws + r2*96 + 32 + h0) = pay[p*4+r2];
                        *(u64*)(ws + r2*96 + 64 + h0) = paz[p*4+r2];
                    }
                }
                __syncwarp();
                for (int hq = 0; hq < 8; hq++) {
                    float4 xv[4][3];
                    #pragma unroll
                    for (int r2 = 0; r2 < 4; r2++) {
                        xv[r2][0] = wsv4[r2*24 + 0*8 + hq];
                        xv[r2][1] = wsv4[r2*24 + 1*8 + hq];
                        xv[r2][2] = wsv4[r2*24 + 2*8 + hq];
                    }
                    #pragma unroll
                    for (int e = 0; e < 4; e++) {
                        float w = sWv21[(t*32 + hq*4 + e)*32 + lane];
                        u64 ww = pk2(w, w);
                        #pragma unroll
                        for (int r2 = 0; r2 < 4; r2++) {
                            fma2(oxy[r2], pk2(fcomp(xv[r2][0],e), fcomp(xv[r2][1],e)), ww);
                            ozv[r2] += w * fcomp(xv[r2][2], e);
                        }
                    }
                }
            }
            float v2x[4], v2y[4], v2z[4];
            #pragma unroll
            for (int r2 = 0; r2 < 4; r2++) {
                float ox, oy; upk2(ox, oy, oxy[r2]);
                float g = ggf[p*4+r2];
                v2x[r2] = g*ox; v2y[r2] = g*oy; v2z[r2] = g*ozv[r2];
            }
            __syncwarp();
            #pragma unroll
            for (int r2 = 0; r2 < 4; r2++) {
                ws[r2*96 +  0 + lane] = v2x[r2];
                ws[r2*96 + 32 + lane] = v2y[r2];
                ws[r2*96 + 64 + lane] = v2z[r2];
            }
            __syncwarp();
            u64 dxy[4] = {0ull,0ull,0ull,0ull};
            float dzv[4] = {0.f,0.f,0.f,0.f};
            for (int cq = 0; cq < 8; cq++) {
                float4 xv[4][3];
                #pragma unroll
                for (int r2 = 0; r2 < 4; r2++) {
                    xv[r2][0] = wsv4[r2*24 + 0*8 + cq];
                    xv[r2][1] = wsv4[r2*24 + 1*8 + cq];
                    xv[r2][2] = wsv4[r2*24 + 2*8 + cq];
                }
                #pragma unroll
                for (int e = 0; e < 4; e++) {
                    float w = sWd1[(cq*4 + e)*32 + lane];
                    u64 ww = pk2(w, w);
                    #pragma unroll
                    for (int r2 = 0; r2 < 4; r2++) {
                        fma2(dxy[r2], pk2(fcomp(xv[r2][0],e), fcomp(xv[r2][1],e)), ww);
                        dzv[r2] += w * fcomp(xv[r2][2], e);
                    }
                }
            }
            float v3x[4], v3y[4], v3z[4];
            #pragma unroll
            for (int r2 = 0; r2 < 4; r2++) {
                float dx, dy; upk2(dx, dy, dxy[r2]);
                float dz = dzv[r2];
                float dot = v2x[r2]*dx + v2y[r2]*dy + v2z[r2]*dz;
                float dsq = dx*dx + dy*dy + dz*dz;
                float tt  = dot / (dsq + 1e-6f);
                float rx = (dot >= 0.f) ? v2x[r2] : (v2x[r2] - tt*dx);
                float ry = (dot >= 0.f) ? v2y[r2] : (v2y[r2] - tt*dy);
                float rz = (dot >= 0.f) ? v2z[r2] : (v2z[r2] - tt*dz);
                v3x[r2] = 0.2f*v2x[r2] + 0.8f*rx;
                v3y[r2] = 0.2f*v2y[r2] + 0.8f*ry;
                v3z[r2] = 0.2f*v2z[r2] + 0.8f*rz;
            }
            __syncwarp();
            #pragma unroll
            for (int r2 = 0; r2 < 4; r2++) {
                ws[r2*96 +  0 + lane] = v3x[r2];
                ws[r2*96 + 32 + lane] = v3y[r2];
                ws[r2*96 + 64 + lane] = v3z[r2];
            }
            __syncwarp();
            u64 bxy[4] = {0ull,0ull,0ull,0ull};
            float bzv[4] = {0.f,0.f,0.f,0.f};
            for (int cq = 0; cq < 8; cq++) {
                float4 xv[4][3];
                #pragma unroll
                for (int r2 = 0; r2 < 4; r2++) {
                    xv[r2][0] = wsv4[r2*24 + 0*8 + cq];
                    xv[r2][1] = wsv4[r2*24 + 1*8 + cq];
                    xv[r2][2] = wsv4[r2*24 + 2*8 + cq];
                }
                #pragma unroll
                for (int e = 0; e < 4; e++) {
                    float w = sWv12[(cq*4 + e)*32 + lane];
                    u64 ww = pk2(w, w);
                    #pragma unroll
                    for (int r2 = 0; r2 < 4; r2++) {
                        fma2(bxy[r2], pk2(fcomp(xv[r2][0],e), fcomp(xv[r2][1],e)), ww);
                        bzv[r2] += w * fcomp(xv[r2][2], e);
                    }
                }
            }
            float res[4];
            #pragma unroll
            for (int r2 = 0; r2 < 4; r2++) {
                float bx, by; upk2(bx, by, bxy[r2]);
                float bz = bzv[r2];
                float vn2 = sqrtf(bx*bx + by*by + bz*bz);
                float pp = vn2 * w2head;
                #pragma unroll
                for (int off = 16; off > 0; off >>= 1)
                    pp += __shfl_xor_sync(FULLMASK, pp, off);
                if (lane == 0) {
                    int rloc = warp*8 + p*4 + r2;
                    pp += partB_sm[rloc*2 + 0] + partB_sm[rloc*2 + 1];
                }
                res[r2] = pp;
            }
            if (lane == 0) {
                int mb = base + p*4;
                if (mb + 3 < M) {
                    *(float4*)(out + mb) = make_float4(res[0], res[1], res[2], res[3]);
                } else {
                    #pragma unroll
                    for (int r2 = 0; r2 < 4; r2++)
                        if (mb + r2 < M) out[mb + r2] = res[r2];
                }
            }
        }
        __syncthreads();   // per-tile region reads done before next staging
    }
}

extern "C" void kernel_launch(void* const* d_in, const int* in_sizes, int n_in,
                              void* d_out, int out_size)
{
    const float* g_sca  = (const float*)d_in[0];
    const float* g_vec  = (const float*)d_in[1];
    const int*   g_idx  = (const int*)  d_in[2];
    const float* gWv11  = (const float*)d_in[3];
    const float* gWv21  = (const float*)d_in[4];
    const float* gWs1   = (const float*)d_in[5];
    const float* gWg1   = (const float*)d_in[6];
    const float* gbg1   = (const float*)d_in[7];
    const float* gWd1   = (const float*)d_in[8];
    const float* gWv12  = (const float*)d_in[9];
    const float* gWs2   = (const float*)d_in[11];
    float* out = (float*)d_out;
    const int M = in_sizes[2];

    cudaFuncSetAttribute(frontier_vn_kernel,
                         cudaFuncAttributeMaxDynamicSharedMemorySize, SMEM_BYTES);
    int sms = 148;
    cudaDeviceGetAttribute(&sms, cudaDevAttrMultiProcessorCount, 0);

    frontier_vn_kernel<<<sms, THREADS, SMEM_BYTES>>>(
        g_sca, g_vec, g_idx,
        gWv11, gWv21, gWs1, gWg1, gbg1, gWd1, gWv12, gWs2,
        out, M);
}

// round 16
// speedup vs baseline: 1.2443x; 1.2443x over previous
#include <cuda_runtime.h>
#include <cuda_fp16.h>
#include <cstdint>

#define NWARPS 12
#define THREADS 384
#define FULLMASK 0xffffffffu

// ---- smem byte map ----
// [0, 62976)       A-tile fp16 [96 x 328h] (stride 656 B) during stage B;
//                  after MMA reused as:
//                    [0, 13824)      gate pre-sigmoid fp32 [96 x 36]
//                    [16384, 17152)  partB_sm [96 x 2] fp32
// [62976, 167936)  BT = [Ws1 | Ws1@Wg1]^T fp16 [160 x 328h] (stride 656 B)
// [167936, 201472) fp32 weights (8384 floats; Wg1 not kept)
// [201472, 219904) scratch: 12 warps x 384 floats
#define AB_OFF     0
#define A_STRIDE_B 656
#define GOUT_STRIDE 36
#define PB_OFF     16384
#define BT_OFF     62976
#define FW_OFF     167936
#define F_WV11     0
#define F_WV21     4096
#define F_BG1      6144
#define F_WD1      6176
#define F_WV12     7200
#define F_WS2      8224
#define SCR_OFF    201472
#define WS_FLOATS  384
#define SMEM_BYTES 219904

typedef unsigned long long u64;
typedef unsigned int u32;

__device__ __forceinline__ u64 pk2(float x, float y){u64 d;asm("mov.b64 %0,{%1,%2};":"=l"(d):"f"(x),"f"(y));return d;}
__device__ __forceinline__ void upk2(float&x,float&y,u64 d){asm("mov.b64 {%0,%1},%2;":"=f"(x),"=f"(y):"l"(d));}
__device__ __forceinline__ void fma2(u64&a,u64 x,u64 w){asm("fma.rn.f32x2 %0,%1,%2,%3;":"=l"(a):"l"(x),"l"(w),"l"(a));}
__device__ __forceinline__ float fcomp(const float4&v,int e){return (&v.x)[e];}
__device__ __forceinline__ float lrelu(float x){return (x>=0.f)?x:0.01f*x;}

__device__ __forceinline__ u32 smem_u32(const void* p){
    u32 a; asm("{ .reg .u64 t; cvta.to.shared.u64 t, %1; cvt.u32.u64 %0, t; }":"=r"(a):"l"(p)); return a;
}
__device__ __forceinline__ void ldm_x4(u32& r0,u32& r1,u32& r2,u32& r3,u32 addr){
    asm volatile("ldmatrix.sync.aligned.m8n8.x4.shared.b16 {%0,%1,%2,%3}, [%4];"
        : "=r"(r0),"=r"(r1),"=r"(r2),"=r"(r3) : "r"(addr));
}
__device__ __forceinline__ void mma16816(float* c,u32 a0,u32 a1,u32 a2,u32 a3,u32 b0,u32 b1){
    asm volatile("mma.sync.aligned.m16n8k16.row.col.f32.f16.f16.f32 "
        "{%0,%1,%2,%3},{%4,%5,%6,%7},{%8,%9},{%0,%1,%2,%3};"
        : "+f"(c[0]),"+f"(c[1]),"+f"(c[2]),"+f"(c[3])
        : "r"(a0),"r"(a1),"r"(a2),"r"(a3),"r"(b0),"r"(b1));
}

__global__ __launch_bounds__(THREADS, 1)
void frontier_vn_kernel(
    const float* __restrict__ g_sca, const float* __restrict__ g_vec,
    const int* __restrict__ g_idx,
    const float* __restrict__ gWv11, const float* __restrict__ gWv21,
    const float* __restrict__ gWs1,  const float* __restrict__ gWg1,
    const float* __restrict__ gbg1,  const float* __restrict__ gWd1,
    const float* __restrict__ gWv12, const float* __restrict__ gWs2,
    float* __restrict__ out, int M)
{
    extern __shared__ char smc[];
    float* fw    = (float*)(smc + FW_OFF);
    float* sWv11 = fw + F_WV11;
    float* sWv21 = fw + F_WV21;
    float* sbg1  = fw + F_BG1;
    float* sWd1  = fw + F_WD1;
    float* sWv12 = fw + F_WV12;
    float* sWs2  = fw + F_WS2;
    float* gate_sm  = (float*)(smc + AB_OFF);
    float* partB_sm = (float*)(smc + PB_OFF);

    const int tid = threadIdx.x, warp = tid>>5, lane = tid&31;
    const u32 sbu = smem_u32(smc);

    // ---- one-time init ----
    // BT rows 0..128 = Ws1^T fp16
    for (int i = tid; i < 40960; i += THREADS) {
        int k = i >> 7, j = i & 127;
        *(__half*)(smc + BT_OFF + j*A_STRIDE_B + k*2) = __float2half(gWs1[i]);
    }
    // BT rows 128..160 = (Ws1 @ Wg1)^T fp16  (composed in fp32)
    for (int i = tid; i < 320*32; i += THREADS) {
        int k = i >> 5, n2 = i & 31;
        float acc = 0.f;
        const float* wr = gWs1 + k*128;
        #pragma unroll 8
        for (int j = 0; j < 128; j++)
            acc += wr[j] * gWg1[j*32 + n2];
        *(__half*)(smc + BT_OFF + (128 + n2)*A_STRIDE_B + k*2) = __float2half(acc);
    }
    {
        float4* d; const float4* s;
        d=(float4*)sWv11; s=(const float4*)gWv11; for(int i=tid;i<1024;i+=THREADS) d[i]=s[i];
        d=(float4*)sWv21; s=(const float4*)gWv21; for(int i=tid;i<512; i+=THREADS) d[i]=s[i];
        d=(float4*)sbg1;  s=(const float4*)gbg1;  for(int i=tid;i<8;   i+=THREADS) d[i]=s[i];
        d=(float4*)sWd1;  s=(const float4*)gWd1;  for(int i=tid;i<256; i+=THREADS) d[i]=s[i];
        d=(float4*)sWv12; s=(const float4*)gWv12; for(int i=tid;i<256; i+=THREADS) d[i]=s[i];
        d=(float4*)sWs2;  s=(const float4*)gWs2;  for(int i=tid;i<40;  i+=THREADS) d[i]=s[i];
    }
    __syncthreads();

    float* ws = (float*)(smc + SCR_OFF) + warp * WS_FLOATS;
    float4* wsv4 = (float4*)ws;
    const float2* sWv11_f2 = (const float2*)sWv11;
    const float4* g_sca4 = (const float4*)g_sca;
    const float4* g_vec4 = (const float4*)g_vec;

    const int r_ln = lane >> 2, q_ln = lane & 3;
    const int pblk = warp >> 1;      // 16-row block
    const int jhalf = warp & 1;      // 80-col half of the 160-wide output
    const float w2head = sWs2[lane];

    // ldmatrix bases (A/B patterns verified in v14)
    const u32 a_base = sbu + AB_OFF
        + (u32)(pblk*16 + (lane&7) + ((lane>>3)&1)*8) * A_STRIDE_B
        + (u32)(lane>>4) * 16;
    const u32 b_base = sbu + BT_OFF
        + (u32)(jhalf*80 + (lane&7) + (lane>>4)*8) * A_STRIDE_B
        + (u32)((lane>>3)&1) * 16;

    for (int tile = blockIdx.x * 96; tile < M; tile += gridDim.x * 96)
    {
        const int base = tile + warp * 8;
        int m_dyn = base + r_ln;
        const int idx_dyn = g_idx[(m_dyn < M) ? m_dyn : (M - 1)];
        const size_t vbase = (size_t)idx_dyn * 48;
        const size_t sbase = (size_t)idx_dyn * 64;

        // ===== Stage A (v5): vec -> vh in registers =====
        u64 pax[8], pay[8], paz[8];
        #pragma unroll
        for (int r = 0; r < 8; r++) { pax[r]=0ull; pay[r]=0ull; paz[r]=0ull; }
        float4 vf0 = g_vec4[vbase + 3*q_ln + 0];
        float4 vf1 = g_vec4[vbase + 3*q_ln + 1];
        float4 vf2 = g_vec4[vbase + 3*q_ln + 2];
        for (int chunk = 0; chunk < 4; chunk++) {
            __syncwarp();
            wsv4[r_ln*12 + 3*q_ln + 0] = vf0;
            wsv4[r_ln*12 + 3*q_ln + 1] = vf1;
            wsv4[r_ln*12 + 3*q_ln + 2] = vf2;
            if (chunk < 3) {
                vf0 = g_vec4[vbase + (chunk+1)*12 + 3*q_ln + 0];
                vf1 = g_vec4[vbase + (chunk+1)*12 + 3*q_ln + 1];
                vf2 = g_vec4[vbase + (chunk+1)*12 + 3*q_ln + 2];
            }
            __syncwarp();
            for (int cq = 0; cq < 4; cq++) {
                u64 ww[4];
                #pragma unroll
                for (int e = 0; e < 4; e++) {
                    float2 w2 = sWv11_f2[(chunk*16 + cq*4 + e)*32 + lane];
                    ww[e] = pk2(w2.x, w2.y);
                }
                #pragma unroll
                for (int r = 0; r < 8; r++) {
                    float4 f0 = wsv4[r*12 + 3*cq + 0];
                    float4 f1 = wsv4[r*12 + 3*cq + 1];
                    float4 f2 = wsv4[r*12 + 3*cq + 2];
                    float vcx[4] = {f0.x, f0.w, f1.z, f2.y};
                    float vcy[4] = {f0.y, f1.x, f1.w, f2.z};
                    float vcz[4] = {f0.z, f1.y, f2.x, f2.w};
                    #pragma unroll
                    for (int e = 0; e < 4; e++) {
                        fma2(pax[r], pk2(vcx[e], vcx[e]), ww[e]);
                        fma2(pay[r], pk2(vcy[e], vcy[e]), ww[e]);
                        fma2(paz[r], pk2(vcz[e], vcz[e]), ww[e]);
                    }
                }
            }
        }

        // ===== A-tile staging (fp16, row-major, stride 656 B) =====
        #pragma unroll
        for (int r = 0; r < 8; r++) {
            float x0,x1,y0,y1,z0,z1;
            upk2(x0,x1,pax[r]); upk2(y0,y1,pay[r]); upk2(z0,z1,paz[r]);
            __half2 nn = __floats2half2_rn(sqrtf(x0*x0+y0*y0+z0*z0),
                                           sqrtf(x1*x1+y1*y1+z1*z1));
            *(__half2*)(smc + (warp*8 + r)*A_STRIDE_B + lane*4) = nn;
        }
        {
            const int mrow = warp*8 + r_ln;
            #pragma unroll
            for (int pass = 0; pass < 8; pass++) {
                float4 a = g_sca4[sbase + pass*8 + q_ln*2];
                float4 b = g_sca4[sbase + pass*8 + q_ln*2 + 1];
                __half2 h0 = __floats2half2_rn(a.x, a.y);
                __half2 h1 = __floats2half2_rn(a.z, a.w);
                __half2 h2 = __floats2half2_rn(b.x, b.y);
                __half2 h3 = __floats2half2_rn(b.z, b.w);
                uint4 v;
                v.x = *(u32*)&h0; v.y = *(u32*)&h1;
                v.z = *(u32*)&h2; v.w = *(u32*)&h3;
                *(uint4*)(smc + mrow*A_STRIDE_B + 128 + pass*64 + q_ln*16) = v;
            }
        }
        __syncthreads();

        // ===== Stage B+gate fused: HMMA [96x320] @ [320x160] =====
        // warp: rows [pblk*16,+16) x cols [jhalf*80,+80)
        float cacc[40];
        #pragma unroll
        for (int i = 0; i < 40; i++) cacc[i] = 0.f;
        #pragma unroll
        for (int ks = 0; ks < 20; ks++) {
            u32 a0,a1,a2,a3;
            ldm_x4(a0,a1,a2,a3, a_base + ks*32);
            #pragma unroll
            for (int nb2 = 0; nb2 < 5; nb2++) {
                u32 b0,b1,b2,b3;
                ldm_x4(b0,b1,b2,b3, b_base + nb2*(16*A_STRIDE_B) + ks*32);
                mma16816(cacc + (nb2*2+0)*4, a0,a1,a2,a3, b0,b1);
                mma16816(cacc + (nb2*2+1)*4, a0,a1,a2,a3, b2,b3);
            }
        }
        __syncthreads();   // all ldmatrix A reads done; region becomes gate/partB

        // ===== fragment epilogue: partB + gate staging, straight from cacc =====
        {
            int row0 = pblk*16 + (lane>>2);
            float pa = 0.f, pb = 0.f;
            #pragma unroll
            for (int nb = 0; nb < 10; nb++) {
                int ncol = jhalf*80 + nb*8 + 2*(lane&3);
                float c0 = cacc[nb*4+0], c1 = cacc[nb*4+1];
                float c2 = cacc[nb*4+2], c3 = cacc[nb*4+3];
                if (ncol < 128) {   // s1 columns -> partB
                    float2 wt = *(const float2*)(sWs2 + 32 + ncol);
                    pa += lrelu(c0)*wt.x + lrelu(c1)*wt.y;
                    pb += lrelu(c2)*wt.x + lrelu(c3)*wt.y;
                } else {            // gate pre-sigmoid columns
                    int gcol = ncol - 128;
                    *(float2*)(gate_sm + row0*GOUT_STRIDE + gcol)     = make_float2(c0, c1);
                    *(float2*)(gate_sm + (row0+8)*GOUT_STRIDE + gcol) = make_float2(c2, c3);
                }
            }
            pa += __shfl_xor_sync(FULLMASK, pa, 1);
            pa += __shfl_xor_sync(FULLMASK, pa, 2);
            pb += __shfl_xor_sync(FULLMASK, pb, 1);
            pb += __shfl_xor_sync(FULLMASK, pb, 2);
            if ((lane & 3) == 0) {
                partB_sm[row0*2 + jhalf]     = pa;
                partB_sm[(row0+8)*2 + jhalf] = pb;
            }
        }
        __syncthreads();

        // sigmoid: warp reads its 8 rows, col = lane
        float ggf[8];
        {
            float bias = sbg1[lane];
            #pragma unroll
            for (int r = 0; r < 8; r++) {
                float g = gate_sm[(warp*8 + r)*GOUT_STRIDE + lane];
                ggf[r] = 1.f/(1.f+__expf(-(g + bias)));
            }
        }

        // ===== Stages D/E/F (v5) =====
        #pragma unroll
        for (int p = 0; p < 2; p++) {
            u64 oxy[4] = {0ull,0ull,0ull,0ull};
            float ozv[4] = {0.f,0.f,0.f,0.f};
            #pragma unroll
            for (int t = 0; t < 2; t++) {
                __syncwarp();
                if ((lane >> 4) == t) {
                    int h0 = 2*lane - 32*t;
                    #pragma unroll
                    for (int r2 = 0; r2 < 4; r2++) {
                        *(u64*)(ws + r2*96 +  0 + h0) = pax[p*4+r2];
                        *(u64*)(ws + r2*96 + 32 + h0) = pay[p*4+r2];
                        *(u64*)(ws + r2*96 + 64 + h0) = paz[p*4+r2];
                    }
                }
                __syncwarp();
                for (int hq = 0; hq < 8; hq++) {
                    float4 xv[4][3];
                    #pragma unroll
                    for (int r2 = 0; r2 < 4; r2++) {
                        xv[r2][0] = wsv4[r2*24 + 0*8 + hq];
                        xv[r2][1] = wsv4[r2*24 + 1*8 + hq];
                        xv[r2][2] = wsv4[r2*24 + 2*8 + hq];
                    }
                    #pragma unroll
                    for (int e = 0; e < 4; e++) {
                        float w = sWv21[(t*32 + hq*4 + e)*32 + lane];
                        u64 ww = pk2(w, w);
                        #pragma unroll
                        for (int r2 = 0; r2 < 4; r2++) {
                            fma2(oxy[r2], pk2(fcomp(xv[r2][0],e), fcomp(xv[r2][1],e)), ww);
                            ozv[r2] += w * fcomp(xv[r2][2], e);
                        }
                    }
                }
            }
            float v2x[4], v2y[4], v2z[4];
            #pragma unroll
            for (int r2 = 0; r2 < 4; r2++) {
                float ox, oy; upk2(ox, oy, oxy[r2]);
                float g = ggf[p*4+r2];
                v2x[r2] = g*ox; v2y[r2] = g*oy; v2z[r2] = g*ozv[r2];
            }
            __syncwarp();
            #pragma unroll
            for (int r2 = 0; r2 < 4; r2++) {
                ws[r2*96 +  0 + lane] = v2x[r2];
                ws[r2*96 + 32 + lane] = v2y[r2];
                ws[r2*96 + 64 + lane] = v2z[r2];
            }
            __syncwarp();
            u64 dxy[4] = {0ull,0ull,0ull,0ull};
            float dzv[4] = {0.f,0.f,0.f,0.f};
            for (int cq = 0; cq < 8; cq++) {
                float4 xv[4][3];
                #pragma unroll
                for (int r2 = 0; r2 < 4; r2++) {
                    xv[r2][0] = wsv4[r2*24 + 0*8 + cq];
                    xv[r2][1] = wsv4[r2*24 + 1*8 + cq];
                    xv[r2][2] = wsv4[r2*24 + 2*8 + cq];
                }
                #pragma unroll
                for (int e = 0; e < 4; e++) {
                    float w = sWd1[(cq*4 + e)*32 + lane];
                    u64 ww = pk2(w, w);
                    #pragma unroll
                    for (int r2 = 0; r2 < 4; r2++) {
                        fma2(dxy[r2], pk2(fcomp(xv[r2][0],e), fcomp(xv[r2][1],e)), ww);
                        dzv[r2] += w * fcomp(xv[r2][2], e);
                    }
                }
            }
            float v3x[4], v3y[4], v3z[4];
            #pragma unroll
            for (int r2 = 0; r2 < 4; r2++) {
                float dx, dy; upk2(dx, dy, dxy[r2]);
                float dz = dzv[r2];
                float dot = v2x[r2]*dx + v2y[r2]*dy + v2z[r2]*dz;
                float dsq = dx*dx + dy*dy + dz*dz;
                float tt  = dot / (dsq + 1e-6f);
                float rx = (dot >= 0.f) ? v2x[r2] : (v2x[r2] - tt*dx);
                float ry = (dot >= 0.f) ? v2y[r2] : (v2y[r2] - tt*dy);
                float rz = (dot >= 0.f) ? v2z[r2] : (v2z[r2] - tt*dz);
                v3x[r2] = 0.2f*v2x[r2] + 0.8f*rx;
                v3y[r2] = 0.2f*v2y[r2] + 0.8f*ry;
                v3z[r2] = 0.2f*v2z[r2] + 0.8f*rz;
            }
            __syncwarp();
            #pragma unroll
            for (int r2 = 0; r2 < 4; r2++) {
                ws[r2*96 +  0 + lane] = v3x[r2];
                ws[r2*96 + 32 + lane] = v3y[r2];
                ws[r2*96 + 64 + lane] = v3z[r2];
            }
            __syncwarp();
            u64 bxy[4] = {0ull,0ull,0ull,0ull};
            float bzv[4] = {0.f,0.f,0.f,0.f};
            for (int cq = 0; cq < 8; cq++) {
                float4 xv[4][3];
                #pragma unroll
                for (int r2 = 0; r2 < 4; r2++) {
                    xv[r2][0] = wsv4[r2*24 + 0*8 + cq];
                    xv[r2][1] = wsv4[r2*24 + 1*8 + cq];
                    xv[r2][2] = wsv4[r2*24 + 2*8 + cq];
                }
                #pragma unroll
                for (int e = 0; e < 4; e++) {
                    float w = sWv12[(cq*4 + e)*32 + lane];
                    u64 ww = pk2(w, w);
                    #pragma unroll
                    for (int r2 = 0; r2 < 4; r2++) {
                        fma2(bxy[r2], pk2(fcomp(xv[r2][0],e), fcomp(xv[r2][1],e)), ww);
                        bzv[r2] += w * fcomp(xv[r2][2], e);
                    }
                }
            }
            float res[4];
            #pragma unroll
            for (int r2 = 0; r2 < 4; r2++) {
                float bx, by; upk2(bx, by, bxy[r2]);
                float bz = bzv[r2];
                float vn2 = sqrtf(bx*bx + by*by + bz*bz);
                float pp = vn2 * w2head;
                #pragma unroll
                for (int off = 16; off > 0; off >>= 1)
                    pp += __shfl_xor_sync(FULLMASK, pp, off);
                if (lane == 0) {
                    int rloc = warp*8 + p*4 + r2;
                    pp += partB_sm[rloc*2 + 0] + partB_sm[rloc*2 + 1];
                }
                res[r2] = pp;
            }
            if (lane == 0) {
                int mb = base + p*4;
                if (mb + 3 < M) {
                    *(float4*)(out + mb) = make_float4(res[0], res[1], res[2], res[3]);
                } else {
                    #pragma unroll
                    for (int r2 = 0; r2 < 4; r2++)
                        if (mb + r2 < M) out[mb + r2] = res[r2];
                }
            }
        }
        __syncthreads();   // gate/partB reads done before next tile's A staging
    }
}

extern "C" void kernel_launch(void* const* d_in, const int* in_sizes, int n_in,
                              void* d_out, int out_size)
{
    const float* g_sca  = (const float*)d_in[0];
    const float* g_vec  = (const float*)d_in[1];
    const int*   g_idx  = (const int*)  d_in[2];
    const float* gWv11  = (const float*)d_in[3];
    const float* gWv21  = (const float*)d_in[4];
    const float* gWs1   = (const float*)d_in[5];
    const float* gWg1   = (const float*)d_in[6];
    const float* gbg1   = (const float*)d_in[7];
    const float* gWd1   = (const float*)d_in[8];
    const float* gWv12  = (const float*)d_in[9];
    const float* gWs2   = (const float*)d_in[11];
    float* out = (float*)d_out;
    const int M = in_sizes[2];

    cudaFuncSetAttribute(frontier_vn_kernel,
                         cudaFuncAttributeMaxDynamicSharedMemorySize, SMEM_BYTES);
    int sms = 148;
    cudaDeviceGetAttribute(&sms, cudaDevAttrMultiProcessorCount, 0);

    frontier_vn_kernel<<<sms, THREADS, SMEM_BYTES>>>(
        g_sca, g_vec, g_idx,
        gWv11, gWv21, gWs1, gWg1, gbg1, gWd1, gWv12, gWs2,
        out, M);
}

// round 17
// speedup vs baseline: 1.4002x; 1.1254x over previous
#include <cuda_runtime.h>
#include <cuda_fp16.h>
#include <cstdint>

#define NWARPS 12
#define THREADS 384
#define FULLMASK 0xffffffffu

// ---- smem byte map ----
// [0, 62976)        A-tile fp16 [96 x 328h] (stride 656 B); after MMA reused
//                   as s1 tile fp32 [96 x 132]
// [62976, 146944)   BT = Ws1^T fp16 [128 x 328h]
// [146944, 205056)  fp32 weights (14528 floats, incl composed W12 = Wv11@Wv21)
// [205056, 223488)  scratch: 12 warps x 384 floats
#define AB_OFF    0
#define A_STRIDE_B 656
#define S1_STRIDE_F 132
#define BT_OFF    62976
#define FW_OFF    146944
#define F_WV11    0
#define F_WV21    4096
#define F_WG1     6144
#define F_BG1     10240
#define F_WD1     10272
#define F_WV12    11296
#define F_WS2     12320
#define F_W12     12480
#define SCR_OFF   205056
#define WS_FLOATS 384
#define SMEM_BYTES 223488

typedef unsigned long long u64;
typedef unsigned int u32;

__device__ __forceinline__ u64 pk2(float x, float y){u64 d;asm("mov.b64 %0,{%1,%2};":"=l"(d):"f"(x),"f"(y));return d;}
__device__ __forceinline__ void upk2(float&x,float&y,u64 d){asm("mov.b64 {%0,%1},%2;":"=f"(x),"=f"(y):"l"(d));}
__device__ __forceinline__ void fma2(u64&a,u64 x,u64 w){asm("fma.rn.f32x2 %0,%1,%2,%3;":"=l"(a):"l"(x),"l"(w),"l"(a));}
__device__ __forceinline__ float fcomp(const float4&v,int e){return (&v.x)[e];}
__device__ __forceinline__ float lrelu(float x){return (x>=0.f)?x:0.01f*x;}

__device__ __forceinline__ u32 smem_u32(const void* p){
    u32 a; asm("{ .reg .u64 t; cvta.to.shared.u64 t, %1; cvt.u32.u64 %0, t; }":"=r"(a):"l"(p)); return a;
}
__device__ __forceinline__ void ldm_x4(u32& r0,u32& r1,u32& r2,u32& r3,u32 addr){
    asm volatile("ldmatrix.sync.aligned.m8n8.x4.shared.b16 {%0,%1,%2,%3}, [%4];"
        : "=r"(r0),"=r"(r1),"=r"(r2),"=r"(r3) : "r"(addr));
}
__device__ __forceinline__ void mma16816(float* c,u32 a0,u32 a1,u32 a2,u32 a3,u32 b0,u32 b1){
    asm volatile("mma.sync.aligned.m16n8k16.row.col.f32.f16.f16.f32 "
        "{%0,%1,%2,%3},{%4,%5,%6,%7},{%8,%9},{%0,%1,%2,%3};"
        : "+f"(c[0]),"+f"(c[1]),"+f"(c[2]),"+f"(c[3])
        : "r"(a0),"r"(a1),"r"(a2),"r"(a3),"r"(b0),"r"(b1));
}

__global__ __launch_bounds__(THREADS, 1)
void frontier_vn_kernel(
    const float* __restrict__ g_sca, const float* __restrict__ g_vec,
    const int* __restrict__ g_idx,
    const float* __restrict__ gWv11, const float* __restrict__ gWv21,
    const float* __restrict__ gWs1,  const float* __restrict__ gWg1,
    const float* __restrict__ gbg1,  const float* __restrict__ gWd1,
    const float* __restrict__ gWv12, const float* __restrict__ gWs2,
    float* __restrict__ out, int M)
{
    extern __shared__ char smc[];
    float* fw    = (float*)(smc + FW_OFF);
    float* sWv11 = fw + F_WV11;
    float* sWg1  = fw + F_WG1;
    float* sbg1  = fw + F_BG1;
    float* sWd1  = fw + F_WD1;
    float* sWv12 = fw + F_WV12;
    float* sWs2  = fw + F_WS2;
    float* sW12  = fw + F_W12;
    float* s1f   = (float*)(smc + AB_OFF);

    const int tid = threadIdx.x, warp = tid>>5, lane = tid&31;
    const u32 sbu = smem_u32(smc);

    // ---- one-time init ----
    for (int i = tid; i < 40960; i += THREADS) {        // BT = Ws1^T fp16
        int k = i >> 7, j = i & 127;
        *(__half*)(smc + BT_OFF + j*A_STRIDE_B + k*2) = __float2half(gWs1[i]);
    }
    for (int i = tid; i < 2048; i += THREADS) {         // W12 = Wv11 @ Wv21 (fp32)
        int c = i >> 5, o = i & 31;
        float acc = 0.f;
        #pragma unroll 8
        for (int h = 0; h < 64; h++)
            acc += gWv11[c*64 + h] * gWv21[h*32 + o];
        sW12[c*32 + o] = acc;
    }
    {
        float4* d; const float4* s;
        d=(float4*)sWv11; s=(const float4*)gWv11; for(int i=tid;i<1024;i+=THREADS) d[i]=s[i];
        d=(float4*)sWg1;  s=(const float4*)gWg1;  for(int i=tid;i<1024;i+=THREADS) d[i]=s[i];
        d=(float4*)sbg1;  s=(const float4*)gbg1;  for(int i=tid;i<8;   i+=THREADS) d[i]=s[i];
        d=(float4*)sWd1;  s=(const float4*)gWd1;  for(int i=tid;i<256; i+=THREADS) d[i]=s[i];
        d=(float4*)sWv12; s=(const float4*)gWv12; for(int i=tid;i<256; i+=THREADS) d[i]=s[i];
        d=(float4*)sWs2;  s=(const float4*)gWs2;  for(int i=tid;i<40;  i+=THREADS) d[i]=s[i];
    }
    __syncthreads();

    float* ws = (float*)(smc + SCR_OFF) + warp * WS_FLOATS;
    float4* wsv4 = (float4*)ws;
    const float2* sWv11_f2 = (const float2*)sWv11;
    const float4* g_sca4 = (const float4*)g_sca;
    const float4* g_vec4 = (const float4*)g_vec;

    const int r_ln = lane >> 2, q_ln = lane & 3;
    const int pblk = warp >> 1;      // 16-row block
    const int jhalf = warp & 1;      // 64-col half
    const float w2head = sWs2[lane];

    // ldmatrix bases (verified in v14)
    const u32 a_base = sbu + AB_OFF
        + (u32)(pblk*16 + (lane&7) + ((lane>>3)&1)*8) * A_STRIDE_B
        + (u32)(lane>>4) * 16;
    const u32 b_base = sbu + BT_OFF
        + (u32)(jhalf*64 + (lane&7) + (lane>>4)*8) * A_STRIDE_B
        + (u32)((lane>>3)&1) * 16;

    for (int tile = blockIdx.x * 96; tile < M; tile += gridDim.x * 96)
    {
        const int base = tile + warp * 8;
        int m_dyn = base + r_ln;
        const int idx_dyn = g_idx[(m_dyn < M) ? m_dyn : (M - 1)];
        const size_t vbase = (size_t)idx_dyn * 48;
        const size_t sbase = (size_t)idx_dyn * 64;

        // ===== Stage A+D fused: vec -> vh (pax) AND ov = vec @ W12 =====
        u64 pax[8], pay[8], paz[8];
        u64 oxy[8];
        float ozv[8];
        #pragma unroll
        for (int r = 0; r < 8; r++) {
            pax[r]=0ull; pay[r]=0ull; paz[r]=0ull;
            oxy[r]=0ull; ozv[r]=0.f;
        }
        float4 vf0 = g_vec4[vbase + 3*q_ln + 0];
        float4 vf1 = g_vec4[vbase + 3*q_ln + 1];
        float4 vf2 = g_vec4[vbase + 3*q_ln + 2];
        for (int chunk = 0; chunk < 4; chunk++) {
            __syncwarp();
            wsv4[r_ln*12 + 3*q_ln + 0] = vf0;
            wsv4[r_ln*12 + 3*q_ln + 1] = vf1;
            wsv4[r_ln*12 + 3*q_ln + 2] = vf2;
            if (chunk < 3) {
                vf0 = g_vec4[vbase + (chunk+1)*12 + 3*q_ln + 0];
                vf1 = g_vec4[vbase + (chunk+1)*12 + 3*q_ln + 1];
                vf2 = g_vec4[vbase + (chunk+1)*12 + 3*q_ln + 2];
            }
            __syncwarp();
            for (int cq = 0; cq < 4; cq++) {
                u64 ww[4], ww12[4];
                float w12s[4];
                #pragma unroll
                for (int e = 0; e < 4; e++) {
                    int c = chunk*16 + cq*4 + e;
                    float2 w2 = sWv11_f2[c*32 + lane];
                    ww[e] = pk2(w2.x, w2.y);
                    float wv = sW12[c*32 + lane];
                    w12s[e] = wv;
                    ww12[e] = pk2(wv, wv);
                }
                #pragma unroll
                for (int r = 0; r < 8; r++) {
                    float4 f0 = wsv4[r*12 + 3*cq + 0];
                    float4 f1 = wsv4[r*12 + 3*cq + 1];
                    float4 f2 = wsv4[r*12 + 3*cq + 2];
                    float vcx[4] = {f0.x, f0.w, f1.z, f2.y};
                    float vcy[4] = {f0.y, f1.x, f1.w, f2.z};
                    float vcz[4] = {f0.z, f1.y, f2.x, f2.w};
                    #pragma unroll
                    for (int e = 0; e < 4; e++) {
                        fma2(pax[r], pk2(vcx[e], vcx[e]), ww[e]);
                        fma2(pay[r], pk2(vcy[e], vcy[e]), ww[e]);
                        fma2(paz[r], pk2(vcz[e], vcz[e]), ww[e]);
                        fma2(oxy[r], pk2(vcx[e], vcy[e]), ww12[e]);
                        ozv[r] += w12s[e] * vcz[e];
                    }
                }
            }
        }

        // ===== A-tile staging (fp16): vn from pax (pax dies here) + sca =====
        #pragma unroll
        for (int r = 0; r < 8; r++) {
            float x0,x1,y0,y1,z0,z1;
            upk2(x0,x1,pax[r]); upk2(y0,y1,pay[r]); upk2(z0,z1,paz[r]);
            __half2 nn = __floats2half2_rn(sqrtf(x0*x0+y0*y0+z0*z0),
                                           sqrtf(x1*x1+y1*y1+z1*z1));
            *(__half2*)(smc + (warp*8 + r)*A_STRIDE_B + lane*4) = nn;
        }
        {
            const int mrow = warp*8 + r_ln;
            #pragma unroll
            for (int pass = 0; pass < 8; pass++) {
                float4 a = g_sca4[sbase + pass*8 + q_ln*2];
                float4 b = g_sca4[sbase + pass*8 + q_ln*2 + 1];
                __half2 h0 = __floats2half2_rn(a.x, a.y);
                __half2 h1 = __floats2half2_rn(a.z, a.w);
                __half2 h2 = __floats2half2_rn(b.x, b.y);
                __half2 h3 = __floats2half2_rn(b.z, b.w);
                uint4 v;
                v.x = *(u32*)&h0; v.y = *(u32*)&h1;
                v.z = *(u32*)&h2; v.w = *(u32*)&h3;
                *(uint4*)(smc + mrow*A_STRIDE_B + 128 + pass*64 + q_ln*16) = v;
            }
        }
        __syncthreads();

        // ===== Stage B: HMMA [pblk*16,+16) x [jhalf*64,+64) =====
        float cacc[32];
        #pragma unroll
        for (int i = 0; i < 32; i++) cacc[i] = 0.f;
        #pragma unroll
        for (int ks = 0; ks < 20; ks++) {
            u32 a0,a1,a2,a3;
            ldm_x4(a0,a1,a2,a3, a_base + ks*32);
            #pragma unroll
            for (int jb2 = 0; jb2 < 4; jb2++) {
                u32 b0,b1,b2,b3;
                ldm_x4(b0,b1,b2,b3, b_base + jb2*(16*A_STRIDE_B) + ks*32);
                mma16816(cacc + (jb2*2+0)*4, a0,a1,a2,a3, b0,b1);
                mma16816(cacc + (jb2*2+1)*4, a0,a1,a2,a3, b2,b3);
            }
        }
        __syncthreads();   // A-tile dead; region becomes s1 fp32

        // ===== write s1 (fp32) =====
        {
            int row0 = pblk*16 + (lane>>2);
            int colb = jhalf*64 + 2*(lane&3);
            #pragma unroll
            for (int jb = 0; jb < 8; jb++) {
                float* p0 = s1f + row0*S1_STRIDE_F + colb + jb*8;
                float* p1 = s1f + (row0+8)*S1_STRIDE_F + colb + jb*8;
                *(float2*)p0 = make_float2(cacc[jb*4+0], cacc[jb*4+1]);
                *(float2*)p1 = make_float2(cacc[jb*4+2], cacc[jb*4+3]);
            }
        }
        __syncthreads();

        // ===== Gate (SIMT from s1 tile, v14) =====
        float ggf[8];
        #pragma unroll
        for (int p2 = 0; p2 < 2; p2++) {
            u64 g01 = 0ull, g23 = 0ull;
            const float4* r0p = (const float4*)(s1f + (warp*8 + p2*4 + 0)*S1_STRIDE_F);
            const float4* r1p = (const float4*)(s1f + (warp*8 + p2*4 + 1)*S1_STRIDE_F);
            const float4* r2p = (const float4*)(s1f + (warp*8 + p2*4 + 2)*S1_STRIDE_F);
            const float4* r3p = (const float4*)(s1f + (warp*8 + p2*4 + 3)*S1_STRIDE_F);
            for (int jq = 0; jq < 32; jq++) {
                float4 x0 = r0p[jq];
                float4 x1 = r1p[jq];
                float4 x2 = r2p[jq];
                float4 x3 = r3p[jq];
                #pragma unroll
                for (int e = 0; e < 4; e++) {
                    float w = sWg1[(jq*4 + e)*32 + lane];
                    u64 ww = pk2(w, w);
                    fma2(g01, pk2(fcomp(x0,e), fcomp(x1,e)), ww);
                    fma2(g23, pk2(fcomp(x2,e), fcomp(x3,e)), ww);
                }
            }
            float a,b,c,d;
            upk2(a,b,g01); upk2(c,d,g23);
            float bias = sbg1[lane];
            ggf[p2*4+0] = 1.f/(1.f+__expf(-(a+bias)));
            ggf[p2*4+1] = 1.f/(1.f+__expf(-(b+bias)));
            ggf[p2*4+2] = 1.f/(1.f+__expf(-(c+bias)));
            ggf[p2*4+3] = 1.f/(1.f+__expf(-(d+bias)));
        }

        // ===== partB (v14): lane = row r_ln, j-slice q_ln*32..+32 =====
        float partBv = 0.f;
        {
            const float4* sp = (const float4*)(s1f + (warp*8 + r_ln)*S1_STRIDE_F) + q_ln*8;
            const float4* wt = (const float4*)(sWs2 + 32) + q_ln*8;
            #pragma unroll
            for (int i = 0; i < 8; i++) {
                float4 sv = sp[i], w = wt[i];
                partBv += lrelu(sv.x)*w.x + lrelu(sv.y)*w.y
                        + lrelu(sv.z)*w.z + lrelu(sv.w)*w.w;
            }
        }

        // ===== Stages E/F per 4-row half (v14, D folded away) =====
        #pragma unroll
        for (int p = 0; p < 2; p++) {
            float v2x[4], v2y[4], v2z[4];
            #pragma unroll
            for (int r2 = 0; r2 < 4; r2++) {
                float ox, oy; upk2(ox, oy, oxy[p*4+r2]);
                float g = ggf[p*4+r2];
                v2x[r2] = g*ox; v2y[r2] = g*oy; v2z[r2] = g*ozv[p*4+r2];
            }

            // ---- E: VNLeakyReLU ----
            __syncwarp();
            #pragma unroll
            for (int r2 = 0; r2 < 4; r2++) {
                ws[r2*96 +  0 + lane] = v2x[r2];
                ws[r2*96 + 32 + lane] = v2y[r2];
                ws[r2*96 + 64 + lane] = v2z[r2];
            }
            __syncwarp();
            u64 dxy[4] = {0ull,0ull,0ull,0ull};
            float dzv[4] = {0.f,0.f,0.f,0.f};
            for (int cq = 0; cq < 8; cq++) {
                float4 xv[4][3];
                #pragma unroll
                for (int r2 = 0; r2 < 4; r2++) {
                    xv[r2][0] = wsv4[r2*24 + 0*8 + cq];
                    xv[r2][1] = wsv4[r2*24 + 1*8 + cq];
                    xv[r2][2] = wsv4[r2*24 + 2*8 + cq];
                }
                #pragma unroll
                for (int e = 0; e < 4; e++) {
                    float w = sWd1[(cq*4 + e)*32 + lane];
                    u64 ww = pk2(w, w);
                    #pragma unroll
                    for (int r2 = 0; r2 < 4; r2++) {
                        fma2(dxy[r2], pk2(fcomp(xv[r2][0],e), fcomp(xv[r2][1],e)), ww);
                        dzv[r2] += w * fcomp(xv[r2][2], e);
                    }
                }
            }
            float v3x[4], v3y[4], v3z[4];
            #pragma unroll
            for (int r2 = 0; r2 < 4; r2++) {
                float dx, dy; upk2(dx, dy, dxy[r2]);
                float dz = dzv[r2];
                float dot = v2x[r2]*dx + v2y[r2]*dy + v2z[r2]*dz;
                float dsq = dx*dx + dy*dy + dz*dz;
                float tt  = dot / (dsq + 1e-6f);
                float rx = (dot >= 0.f) ? v2x[r2] : (v2x[r2] - tt*dx);
                float ry = (dot >= 0.f) ? v2y[r2] : (v2y[r2] - tt*dy);
                float rz = (dot >= 0.f) ? v2z[r2] : (v2z[r2] - tt*dz);
                v3x[r2] = 0.2f*v2x[r2] + 0.8f*rx;
                v3y[r2] = 0.2f*v2y[r2] + 0.8f*ry;
                v3z[r2] = 0.2f*v2z[r2] + 0.8f*rz;
            }
            __syncwarp();
            #pragma unroll
            for (int r2 = 0; r2 < 4; r2++) {
                ws[r2*96 +  0 + lane] = v3x[r2];
                ws[r2*96 + 32 + lane] = v3y[r2];
                ws[r2*96 + 64 + lane] = v3z[r2];
            }
            __syncwarp();
            u64 bxy[4] = {0ull,0ull,0ull,0ull};
            float bzv[4] = {0.f,0.f,0.f,0.f};
            for (int cq = 0; cq < 8; cq++) {
                float4 xv[4][3];
                #pragma unroll
                for (int r2 = 0; r2 < 4; r2++) {
                    xv[r2][0] = wsv4[r2*24 + 0*8 + cq];
                    xv[r2][1] = wsv4[r2*24 + 1*8 + cq];
                    xv[r2][2] = wsv4[r2*24 + 2*8 + cq];
                }
                #pragma unroll
                for (int e = 0; e < 4; e++) {
                    float w = sWv12[(cq*4 + e)*32 + lane];
                    u64 ww = pk2(w, w);
                    #pragma unroll
                    for (int r2 = 0; r2 < 4; r2++) {
                        fma2(bxy[r2], pk2(fcomp(xv[r2][0],e), fcomp(xv[r2][1],e)), ww);
                        bzv[r2] += w * fcomp(xv[r2][2], e);
                    }
                }
            }
            float res[4];
            #pragma unroll
            for (int r2 = 0; r2 < 4; r2++) {
                float bx, by; upk2(bx, by, bxy[r2]);
                float bz = bzv[r2];
                float vn2 = sqrtf(bx*bx + by*by + bz*bz);
                float pb = ((lane>>2) == (p*4+r2)) ? partBv : 0.f;
                float pp = vn2 * w2head + pb;
                #pragma unroll
                for (int off = 16; off > 0; off >>= 1)
                    pp += __shfl_xor_sync(FULLMASK, pp, off);
                res[r2] = pp;
            }
            if (lane == 0) {
                int mb = base + p*4;
                if (mb + 3 < M) {
                    *(float4*)(out + mb) = make_float4(res[0], res[1], res[2], res[3]);
                } else {
                    #pragma unroll
                    for (int r2 = 0; r2 < 4; r2++)
                        if (mb + r2 < M) out[mb + r2] = res[r2];
                }
            }
        }
        __syncthreads();   // s1 tile reads done before next tile's A staging
    }
}

extern "C" void kernel_launch(void* const* d_in, const int* in_sizes, int n_in,
                              void* d_out, int out_size)
{
    const float* g_sca  = (const float*)d_in[0];
    const float* g_vec  = (const float*)d_in[1];
    const int*   g_idx  = (const int*)  d_in[2];
    const float* gWv11  = (const float*)d_in[3];
    const float* gWv21  = (const float*)d_in[4];
    const float* gWs1   = (const float*)d_in[5];
    const float* gWg1   = (const float*)d_in[6];
    const float* gbg1   = (const float*)d_in[7];
    const float* gWd1   = (const float*)d_in[8];
    const float* gWv12  = (const float*)d_in[9];
    const float* gWs2   = (const float*)d_in[11];
    float* out = (float*)d_out;
    const int M = in_sizes[2];

    cudaFuncSetAttribute(frontier_vn_kernel,
                         cudaFuncAttributeMaxDynamicSharedMemorySize, SMEM_BYTES);
    int sms = 148;
    cudaDeviceGetAttribute(&sms, cudaDevAttrMultiProcessorCount, 0);

    frontier_vn_kernel<<<sms, THREADS, SMEM_BYTES>>>(
        g_sca, g_vec, g_idx,
        gWv11, gWv21, gWs1, gWg1, gbg1, gWd1, gWv12, gWs2,
        out, M);
}